// round 10
// baseline (speedup 1.0000x reference)
#include <cuda_runtime.h>

// BiLinearInteractionLayer: out[b, p, :] = (x[b,i_p,:] @ W) * x[b,j_p,:]
// x: [2048, 40, 64] fp32, W: [64, 64] fp32, out: [2048, 780*64] fp32.
//
// One CTA per batch row (best-measured structure, R7 base, 69.66us).
// Thread (col = tid&15, fb = tid>>4) keeps xw rows {fb, 31-fb, 32+fb} in
// registers; streams pair products with one LDS.128 per STG.128.
// R10 delta: __stwt (write-through, no-allocate) stores — the last untested
// store policy. Writes stream to DRAM without dirty-L2 victim scheduling.
// (Tested: __stcs 69.7us, default WB 74.3us, L2-warm x: no effect.)

#define F_NUM   40
#define EDIM    64
#define RPAD    68          // floats per sx row -> bank stride 4 mod 32
#define RPAD4   17
#define NPAIR   780
#define TPB     256
#define BATCH_N 2048

__global__ __launch_bounds__(TPB, 6)
void bilinear_interact_kernel(const float* __restrict__ x,
                              const float* __restrict__ w,
                              float* __restrict__ out)
{
    __shared__ float sx[F_NUM * RPAD];    // 10.6 KB
    __shared__ float sw[EDIM * EDIM];     // 16 KB

    const int b   = blockIdx.x;
    const int tid = threadIdx.x;

    // ---- Phase 1: stage inputs ------------------------------------------
    {
        const float4* xg  = reinterpret_cast<const float4*>(x + (size_t)b * F_NUM * EDIM);
        float4*       sx4 = reinterpret_cast<float4*>(sx);
        #pragma unroll
        for (int t = tid; t < F_NUM * EDIM / 4; t += TPB) {
            const int row = t >> 4;
            const int c   = t & 15;
            sx4[row * RPAD4 + c] = xg[t];
        }
        const float4* wg  = reinterpret_cast<const float4*>(w);
        float4*       sw4 = reinterpret_cast<float4*>(sw);
        #pragma unroll
        for (int t = tid; t < EDIM * EDIM / 4; t += TPB) sw4[t] = wg[t];
    }
    __syncthreads();

    const int col = tid & 15;   // float4 column (d/4)
    const int fb  = tid >> 4;   // 0..15

    const int i0 = fb;          // 0..15
    const int i1 = 31 - fb;     // 16..31
    const int i2 = 32 + fb;     // 32..39, only live for fb < 8

    // ---- Phase 2: xw rows -> registers ----------------------------------
    float4 acc0 = make_float4(0.f, 0.f, 0.f, 0.f);
    float4 acc1 = acc0;
    float4 acc2 = acc0;
    {
        const float4* swv = reinterpret_cast<const float4*>(sw);
        if (fb < 8) {           // warp-uniform: warps 0-3
            #pragma unroll 8
            for (int k = 0; k < EDIM; k++) {
                const float4 wv = swv[k * 16 + col];
                const float a0 = sx[i0 * RPAD + k];
                const float a1 = sx[i1 * RPAD + k];
                const float a2 = sx[i2 * RPAD + k];
                acc0.x += a0 * wv.x; acc0.y += a0 * wv.y; acc0.z += a0 * wv.z; acc0.w += a0 * wv.w;
                acc1.x += a1 * wv.x; acc1.y += a1 * wv.y; acc1.z += a1 * wv.z; acc1.w += a1 * wv.w;
                acc2.x += a2 * wv.x; acc2.y += a2 * wv.y; acc2.z += a2 * wv.z; acc2.w += a2 * wv.w;
            }
        } else {                // warps 4-7: only 2 live rows
            #pragma unroll 8
            for (int k = 0; k < EDIM; k++) {
                const float4 wv = swv[k * 16 + col];
                const float a0 = sx[i0 * RPAD + k];
                const float a1 = sx[i1 * RPAD + k];
                acc0.x += a0 * wv.x; acc0.y += a0 * wv.y; acc0.z += a0 * wv.z; acc0.w += a0 * wv.w;
                acc1.x += a1 * wv.x; acc1.y += a1 * wv.y; acc1.z += a1 * wv.z; acc1.w += a1 * wv.w;
            }
        }
    }
    // No sync: phase 3 reads sx (already sync'd) and registers only.

    // ---- Phase 3: stream pair products from registers --------------------
    // pb(i) = i*(79-i)/2 ; out[b, pb(i)+jo, :] = xw[i] * x[i+1+jo]
    {
        float4*       out4 = reinterpret_cast<float4*>(out + (size_t)b * NPAIR * EDIM);
        const float4* sx4  = reinterpret_cast<const float4*>(sx);

        // row i0
        {
            const int nj = F_NUM - 1 - i0;
            const int pb = (i0 * (2 * F_NUM - 1 - i0)) >> 1;
            float4*       ob = out4 + (size_t)pb * 16 + col;
            const float4* vb = sx4 + (size_t)(i0 + 1) * RPAD4 + col;
            #pragma unroll 4
            for (int jo = 0; jo < nj; jo++) {
                const float4 v = vb[jo * RPAD4];
                __stwt(ob + jo * 16, make_float4(acc0.x * v.x, acc0.y * v.y,
                                                 acc0.z * v.z, acc0.w * v.w));
            }
        }
        // row i1
        {
            const int nj = F_NUM - 1 - i1;
            const int pb = (i1 * (2 * F_NUM - 1 - i1)) >> 1;
            float4*       ob = out4 + (size_t)pb * 16 + col;
            const float4* vb = sx4 + (size_t)(i1 + 1) * RPAD4 + col;
            #pragma unroll 4
            for (int jo = 0; jo < nj; jo++) {
                const float4 v = vb[jo * RPAD4];
                __stwt(ob + jo * 16, make_float4(acc1.x * v.x, acc1.y * v.y,
                                                 acc1.z * v.z, acc1.w * v.w));
            }
        }
        // row i2 (warps 0-3 only; warp-uniform branch)
        if (fb < 8) {
            const int nj = F_NUM - 1 - i2;
            const int pb = (i2 * (2 * F_NUM - 1 - i2)) >> 1;
            float4*       ob = out4 + (size_t)pb * 16 + col;
            const float4* vb = sx4 + (size_t)(i2 + 1) * RPAD4 + col;
            #pragma unroll 4
            for (int jo = 0; jo < nj; jo++) {
                const float4 v = vb[jo * RPAD4];
                __stwt(ob + jo * 16, make_float4(acc2.x * v.x, acc2.y * v.y,
                                                 acc2.z * v.z, acc2.w * v.w));
            }
        }
    }
}

extern "C" void kernel_launch(void* const* d_in, const int* in_sizes, int n_in,
                              void* d_out, int out_size)
{
    const float* x = (const float*)d_in[0];   // [2048, 40, 64]
    const float* w = (const float*)d_in[1];   // [64, 64]
    float* out = (float*)d_out;               // [2048, 780*64]
    (void)in_sizes; (void)n_in; (void)out_size;

    bilinear_interact_kernel<<<BATCH_N, TPB>>>(x, w, out);
}

// round 11
// speedup vs baseline: 1.0902x; 1.0902x over previous
#include <cuda_runtime.h>

// BiLinearInteractionLayer: out[b, p, :] = (x[b,i_p,:] @ W) * x[b,j_p,:]
// x: [2048, 40, 64] fp32, W: [64, 64] fp32, out: [2048, 780*64] fp32.
//
// FINAL (converged, R7 structure, measured 69.66us):
// The kernel is bound by the 409MB output write stream (~5.9 TB/s sustained
// write BW, DRAM when-active ~= spec). Verified by sweep: L1 work 58-87%,
// occupancy 43-76%, wave structure (incl. persistent + cp.async prefetch),
// L2-warmed inputs — all had zero effect on dur. Store policy matters:
// __stcs (evict-first) beats write-back and write-through by ~4.5us.
//
// Structure: one CTA per batch row. Thread (col = tid&15, fb = tid>>4)
// keeps xw rows {fb, 31-fb, 32+fb} in registers (no sxw smem, no pair LUT),
// then streams pair products with exactly one LDS.128 per STG.128.
// Warps 4-7 (fb>=8, warp-uniform) skip the dead third row.

#define F_NUM   40
#define EDIM    64
#define RPAD    68          // floats per sx row -> bank stride 4 mod 32
#define RPAD4   17
#define NPAIR   780
#define TPB     256
#define BATCH_N 2048

__global__ __launch_bounds__(TPB, 6)
void bilinear_interact_kernel(const float* __restrict__ x,
                              const float* __restrict__ w,
                              float* __restrict__ out)
{
    __shared__ float sx[F_NUM * RPAD];    // 10.6 KB
    __shared__ float sw[EDIM * EDIM];     // 16 KB

    const int b   = blockIdx.x;
    const int tid = threadIdx.x;

    // ---- Phase 1: stage inputs ------------------------------------------
    {
        const float4* xg  = reinterpret_cast<const float4*>(x + (size_t)b * F_NUM * EDIM);
        float4*       sx4 = reinterpret_cast<float4*>(sx);
        #pragma unroll
        for (int t = tid; t < F_NUM * EDIM / 4; t += TPB) {
            const int row = t >> 4;
            const int c   = t & 15;
            sx4[row * RPAD4 + c] = xg[t];
        }
        const float4* wg  = reinterpret_cast<const float4*>(w);
        float4*       sw4 = reinterpret_cast<float4*>(sw);
        #pragma unroll
        for (int t = tid; t < EDIM * EDIM / 4; t += TPB) sw4[t] = wg[t];
    }
    __syncthreads();

    const int col = tid & 15;   // float4 column (d/4)
    const int fb  = tid >> 4;   // 0..15

    const int i0 = fb;          // 0..15
    const int i1 = 31 - fb;     // 16..31
    const int i2 = 32 + fb;     // 32..39, only live for fb < 8

    // ---- Phase 2: xw rows -> registers ----------------------------------
    float4 acc0 = make_float4(0.f, 0.f, 0.f, 0.f);
    float4 acc1 = acc0;
    float4 acc2 = acc0;
    {
        const float4* swv = reinterpret_cast<const float4*>(sw);
        if (fb < 8) {           // warp-uniform: warps 0-3
            #pragma unroll 8
            for (int k = 0; k < EDIM; k++) {
                const float4 wv = swv[k * 16 + col];
                const float a0 = sx[i0 * RPAD + k];
                const float a1 = sx[i1 * RPAD + k];
                const float a2 = sx[i2 * RPAD + k];
                acc0.x += a0 * wv.x; acc0.y += a0 * wv.y; acc0.z += a0 * wv.z; acc0.w += a0 * wv.w;
                acc1.x += a1 * wv.x; acc1.y += a1 * wv.y; acc1.z += a1 * wv.z; acc1.w += a1 * wv.w;
                acc2.x += a2 * wv.x; acc2.y += a2 * wv.y; acc2.z += a2 * wv.z; acc2.w += a2 * wv.w;
            }
        } else {                // warps 4-7: only 2 live rows
            #pragma unroll 8
            for (int k = 0; k < EDIM; k++) {
                const float4 wv = swv[k * 16 + col];
                const float a0 = sx[i0 * RPAD + k];
                const float a1 = sx[i1 * RPAD + k];
                acc0.x += a0 * wv.x; acc0.y += a0 * wv.y; acc0.z += a0 * wv.z; acc0.w += a0 * wv.w;
                acc1.x += a1 * wv.x; acc1.y += a1 * wv.y; acc1.z += a1 * wv.z; acc1.w += a1 * wv.w;
            }
        }
    }
    // No sync: phase 3 reads sx (already sync'd) and registers only.

    // ---- Phase 3: stream pair products from registers --------------------
    // pb(i) = i*(79-i)/2 ; out[b, pb(i)+jo, :] = xw[i] * x[i+1+jo]
    {
        float4*       out4 = reinterpret_cast<float4*>(out + (size_t)b * NPAIR * EDIM);
        const float4* sx4  = reinterpret_cast<const float4*>(sx);

        // row i0
        {
            const int nj = F_NUM - 1 - i0;
            const int pb = (i0 * (2 * F_NUM - 1 - i0)) >> 1;
            float4*       ob = out4 + (size_t)pb * 16 + col;
            const float4* vb = sx4 + (size_t)(i0 + 1) * RPAD4 + col;
            #pragma unroll 4
            for (int jo = 0; jo < nj; jo++) {
                const float4 v = vb[jo * RPAD4];
                __stcs(ob + jo * 16, make_float4(acc0.x * v.x, acc0.y * v.y,
                                                 acc0.z * v.z, acc0.w * v.w));
            }
        }
        // row i1
        {
            const int nj = F_NUM - 1 - i1;
            const int pb = (i1 * (2 * F_NUM - 1 - i1)) >> 1;
            float4*       ob = out4 + (size_t)pb * 16 + col;
            const float4* vb = sx4 + (size_t)(i1 + 1) * RPAD4 + col;
            #pragma unroll 4
            for (int jo = 0; jo < nj; jo++) {
                const float4 v = vb[jo * RPAD4];
                __stcs(ob + jo * 16, make_float4(acc1.x * v.x, acc1.y * v.y,
                                                 acc1.z * v.z, acc1.w * v.w));
            }
        }
        // row i2 (warps 0-3 only; warp-uniform branch)
        if (fb < 8) {
            const int nj = F_NUM - 1 - i2;
            const int pb = (i2 * (2 * F_NUM - 1 - i2)) >> 1;
            float4*       ob = out4 + (size_t)pb * 16 + col;
            const float4* vb = sx4 + (size_t)(i2 + 1) * RPAD4 + col;
            #pragma unroll 4
            for (int jo = 0; jo < nj; jo++) {
                const float4 v = vb[jo * RPAD4];
                __stcs(ob + jo * 16, make_float4(acc2.x * v.x, acc2.y * v.y,
                                                 acc2.z * v.z, acc2.w * v.w));
            }
        }
    }
}

extern "C" void kernel_launch(void* const* d_in, const int* in_sizes, int n_in,
                              void* d_out, int out_size)
{
    const float* x = (const float*)d_in[0];   // [2048, 40, 64]
    const float* w = (const float*)d_in[1];   // [64, 64]
    float* out = (float*)d_out;               // [2048, 780*64]
    (void)in_sizes; (void)n_in; (void)out_size;

    bilinear_interact_kernel<<<BATCH_N, TPB>>>(x, w, out);
}